// round 6
// baseline (speedup 1.0000x reference)
#include <cuda_runtime.h>
#include <math.h>
#include <stdint.h>

#define NN 10000
#define DD 512
#define HH 256
#define OO 128
#define CAP 128          // final merged neighbor cap per row
#define CAPH 96          // cap per half (upper / lower)
#define LCAP 16          // per-thread local buffer in scan

// ---------------- scratch (static device memory; no allocations) -------------
__device__ int   g_cols [(size_t)NN * CAP];    // merged neighbor lists
__device__ int   g_cnt  [NN];                  // merged nnz per row
__device__ float g_dinv [NN];                  // rsqrt(degree)
__device__ int   g_colsU[(size_t)NN * CAPH];   // upper-tri neighbors (own scan)
__device__ int   g_cntU [NN];
__device__ int   g_colsL[(size_t)NN * CAPH];   // lower-tri neighbors (atomic scatter)
__device__ int   g_cntL [NN];
__device__ float g_xw  [(size_t)NN * HH];      // u  = dinv .* (x @ W1)
__device__ float g_h   [(size_t)NN * HH];      // hs = dinv .* relu(an @ xw)
__device__ float g_g   [(size_t)NN * HH];      // g  = an @ h

// ---------------- Kernel A: upper-triangle scan ------------------------------
__global__ __launch_bounds__(256)
void k_scan_ut(const float* __restrict__ adj)
{
    const int row = blockIdx.x;
    const int tid = threadIdx.x;
    const uint32_t* __restrict__ arow =
        reinterpret_cast<const uint32_t*>(adj + (size_t)row * NN);

    int local[LCAP];
    int lc = 0;

    const int start = row + 1;
    int aligned = (start + 15) & ~15;
    if (aligned > NN) aligned = NN;

    {
        int c = start + tid;
        if (c < aligned && arow[c] != 0u) { local[lc] = c; lc++; }
    }

    const uint4* __restrict__ arow4 = reinterpret_cast<const uint4*>(arow);
    const int base = aligned >> 4;
    const int nch  = NN >> 4;
    for (int t = base + tid; t < nch; t += 256) {
        const uint4* p = arow4 + 4 * t;
        uint4 w0 = p[0], w1 = p[1], w2 = p[2], w3 = p[3];
        uint32_t m = ((w0.x | w0.y) | (w0.z | w0.w))
                   | ((w1.x | w1.y) | (w1.z | w1.w))
                   | ((w2.x | w2.y) | (w2.z | w2.w))
                   | ((w3.x | w3.y) | (w3.z | w3.w));
        if (m != 0u) {
            const int c0 = t << 4;
            #define CHK(w, off) if ((w) != 0u) { if (lc < LCAP) local[lc] = c0 + (off); lc++; }
            CHK(w0.x, 0)  CHK(w0.y, 1)  CHK(w0.z, 2)  CHK(w0.w, 3)
            CHK(w1.x, 4)  CHK(w1.y, 5)  CHK(w1.z, 6)  CHK(w1.w, 7)
            CHK(w2.x, 8)  CHK(w2.y, 9)  CHK(w2.z, 10) CHK(w2.w, 11)
            CHK(w3.x, 12) CHK(w3.y, 13) CHK(w3.z, 14) CHK(w3.w, 15)
            #undef CHK
        }
    }
    if (lc > LCAP) lc = LCAP;

    __shared__ int s_c[256];
    __shared__ int s_off[256];
    __shared__ int s_total;
    s_c[tid] = lc;
    __syncthreads();
    if (tid == 0) {
        int acc = 0;
        #pragma unroll 8
        for (int i = 0; i < 256; i++) { s_off[i] = acc; acc += s_c[i]; }
        s_total = acc;
    }
    __syncthreads();

    int* __restrict__ ucols = g_colsU + (size_t)row * CAPH;
    int pos = s_off[tid];
    for (int i = 0; i < lc; i++) {
        int c = local[i];
        int p = pos + i;
        if (p < CAPH) ucols[p] = c;
        int lp = atomicAdd(&g_cntL[c], 1);
        if (lp < CAPH) g_colsL[(size_t)c * CAPH + lp] = row;
    }
    if (tid == 0) {
        int total = s_total;
        if (total > CAPH) total = CAPH;
        g_cntU[row] = total;
    }
}

// ---------------- Kernel M: merge L (sorted) + U -> g_cols, cnt, dinv --------
__global__ __launch_bounds__(256)
void k_merge()
{
    const int lane = threadIdx.x & 31;
    const int row  = blockIdx.x * 8 + (threadIdx.x >> 5);
    if (row >= NN) return;

    int cntL = g_cntL[row]; if (cntL > CAPH) cntL = CAPH;
    int cntU = g_cntU[row]; if (cntU > CAPH) cntU = CAPH;
    int total = cntL + cntU; if (total > CAP) total = CAP;

    const int* __restrict__ L = g_colsL + (size_t)row * CAPH;
    const int* __restrict__ U = g_colsU + (size_t)row * CAPH;
    int* __restrict__ dst = g_cols + (size_t)row * CAP;

    for (int s = lane; s < cntL; s += 32) {
        int v = L[s];
        int rank = 0;
        for (int j = 0; j < cntL; j++) rank += (L[j] < v) ? 1 : 0;
        if (rank < CAP) dst[rank] = v;
    }
    for (int k = lane; k < cntU; k += 32) {
        int p = cntL + k;
        if (p < CAP) dst[p] = U[k];
    }
    if (lane == 0) {
        g_cnt[row]  = total;
        g_dinv[row] = rsqrtf((float)total + 1.0f);
    }
}

// ---------------- tf32 helpers ----------------
__device__ __forceinline__ uint32_t f2tf32(float x)
{
    uint32_t r;
    asm("cvt.rna.tf32.f32 %0, %1;" : "=r"(r) : "f"(x));
    return r;
}

__device__ __forceinline__ void mma_tf32(float c[4],
    uint32_t a0, uint32_t a1, uint32_t a2, uint32_t a3,
    uint32_t b0, uint32_t b1)
{
    asm volatile(
        "mma.sync.aligned.m16n8k8.row.col.f32.tf32.tf32.f32 "
        "{%0,%1,%2,%3}, {%4,%5,%6,%7}, {%8,%9}, {%0,%1,%2,%3};"
        : "+f"(c[0]), "+f"(c[1]), "+f"(c[2]), "+f"(c[3])
        : "r"(a0), "r"(a1), "r"(a2), "r"(a3), "r"(b0), "r"(b1));
}

__device__ __forceinline__ int swz(int k)
{
    return ((k & 3) ^ ((k >> 2) & 3)) << 3;
}

// ---------------- Kernel B: tf32 tensor-core GEMM  C = A[M,K] @ B[K,N] ------
// BM=128, BN=128, BK=16, 256 threads (8 warps as 2x4; warp tile 64x32).
// acc 64 regs/thread -> ~130 regs total. Double-buffered smem, reg prefetch.
// DUAL_B: blockIdx.x selects Bm/Bs2 and C half (full-width BN=NDIM=128).
template<int KDIM, bool SCALE_DINV, bool DUAL_B>
__global__ __launch_bounds__(256)
void k_mma(const float* __restrict__ A, const float* __restrict__ Bm,
           const float* __restrict__ Bs2, float* __restrict__ C,
           int M, int NDIM)
{
    const int BM = 128, BN = 128, BK = 16;
    const int NIT = KDIM / BK;
    __shared__ uint32_t As[2][BK * BM];    // 8 KB x2
    __shared__ uint32_t Bsm[2][BK * BN];   // 8 KB x2

    const int tid  = threadIdx.x;
    const int lane = tid & 31;
    const int warp = tid >> 5;
    const int wm   = warp >> 2;          // 0..1 -> 64-row half
    const int wn   = warp & 3;           // 0..3 -> 32-col slice
    const int gid  = lane >> 2;          // 0..7
    const int tig  = lane & 3;           // 0..3

    const int row0 = blockIdx.y * BM;
    const float* __restrict__ B;
    int col0;
    float* __restrict__ Cp;
    if (DUAL_B) {
        B    = blockIdx.x ? Bs2 : Bm;
        col0 = 0;
        Cp   = C + (size_t)blockIdx.x * (size_t)M * NDIM;
    } else {
        B    = Bm;
        col0 = blockIdx.x * BN;
        Cp   = C;
    }

    // loader mappings
    const int a_row = tid >> 1;          // 0..127
    const int a_k8  = (tid & 1) * 8;     // 0 or 8
    const int b_kk  = warp;              // rows warp and warp+8
    const int b_n4  = lane * 4;          // 0..124

    float acc[4][4][4];
    #pragma unroll
    for (int mt = 0; mt < 4; mt++)
        #pragma unroll
        for (int nt = 0; nt < 4; nt++)
            #pragma unroll
            for (int i = 0; i < 4; i++) acc[mt][nt][i] = 0.0f;

    float4 ra0, ra1, rb0, rb1;

    // ---- prologue: load tile 0 ----
    {
        int gr = row0 + a_row;
        ra0 = (gr < M) ? *reinterpret_cast<const float4*>(A + (size_t)gr * KDIM + a_k8)
                       : make_float4(0.f, 0.f, 0.f, 0.f);
        ra1 = (gr < M) ? *reinterpret_cast<const float4*>(A + (size_t)gr * KDIM + a_k8 + 4)
                       : make_float4(0.f, 0.f, 0.f, 0.f);
        rb0 = *reinterpret_cast<const float4*>(B + (size_t)b_kk * NDIM + col0 + b_n4);
        rb1 = *reinterpret_cast<const float4*>(B + (size_t)(b_kk + 8) * NDIM + col0 + b_n4);

        const float* va = &ra0.x;
        const float* vb = &ra1.x;
        #pragma unroll
        for (int i = 0; i < 4; i++) {
            int k = a_k8 + i;
            As[0][k * BM + (a_row ^ swz(k))] = f2tf32(va[i]);
        }
        #pragma unroll
        for (int i = 0; i < 4; i++) {
            int k = a_k8 + 4 + i;
            As[0][k * BM + (a_row ^ swz(k))] = f2tf32(vb[i]);
        }
        const float* w0 = &rb0.x;
        uint32_t* d0 = &Bsm[0][b_kk * BN + (b_n4 ^ swz(b_kk))];
        #pragma unroll
        for (int i = 0; i < 4; i++) d0[i] = f2tf32(w0[i]);
        const float* w1 = &rb1.x;
        uint32_t* d1 = &Bsm[0][(b_kk + 8) * BN + (b_n4 ^ swz(b_kk + 8))];
        #pragma unroll
        for (int i = 0; i < 4; i++) d1[i] = f2tf32(w1[i]);
    }
    __syncthreads();

    int st = 0;
    for (int it = 0; it < NIT; ++it) {
        // prefetch next tile into registers
        if (it + 1 < NIT) {
            int k0 = (it + 1) * BK;
            int gr = row0 + a_row;
            ra0 = (gr < M) ? *reinterpret_cast<const float4*>(A + (size_t)gr * KDIM + k0 + a_k8)
                           : make_float4(0.f, 0.f, 0.f, 0.f);
            ra1 = (gr < M) ? *reinterpret_cast<const float4*>(A + (size_t)gr * KDIM + k0 + a_k8 + 4)
                           : make_float4(0.f, 0.f, 0.f, 0.f);
            rb0 = *reinterpret_cast<const float4*>(B + (size_t)(k0 + b_kk) * NDIM + col0 + b_n4);
            rb1 = *reinterpret_cast<const float4*>(B + (size_t)(k0 + b_kk + 8) * NDIM + col0 + b_n4);
        }

        // compute current stage
        #pragma unroll
        for (int ks = 0; ks < BK; ks += 8) {
            const int k1 = ks + tig;
            const int k2 = ks + tig + 4;
            const int sx1 = swz(k1);
            const int sx2 = swz(k2);

            uint32_t af[4][4];
            #pragma unroll
            for (int mt = 0; mt < 4; mt++) {
                int r1 = wm * 64 + mt * 16 + gid;
                af[mt][0] = As[st][k1 * BM + (r1 ^ sx1)];
                af[mt][1] = As[st][k1 * BM + ((r1 + 8) ^ sx1)];
                af[mt][2] = As[st][k2 * BM + (r1 ^ sx2)];
                af[mt][3] = As[st][k2 * BM + ((r1 + 8) ^ sx2)];
            }
            uint32_t bf[4][2];
            #pragma unroll
            for (int nt = 0; nt < 4; nt++) {
                int cn = wn * 32 + nt * 8 + gid;
                bf[nt][0] = Bsm[st][k1 * BN + (cn ^ sx1)];
                bf[nt][1] = Bsm[st][k2 * BN + (cn ^ sx2)];
            }
            #pragma unroll
            for (int mt = 0; mt < 4; mt++)
                #pragma unroll
                for (int nt = 0; nt < 4; nt++)
                    mma_tf32(acc[mt][nt], af[mt][0], af[mt][1], af[mt][2], af[mt][3],
                             bf[nt][0], bf[nt][1]);
        }

        // store prefetched tile into other stage
        if (it + 1 < NIT) {
            int so = st ^ 1;
            const float* va = &ra0.x;
            const float* vb = &ra1.x;
            #pragma unroll
            for (int i = 0; i < 4; i++) {
                int k = a_k8 + i;
                As[so][k * BM + (a_row ^ swz(k))] = f2tf32(va[i]);
            }
            #pragma unroll
            for (int i = 0; i < 4; i++) {
                int k = a_k8 + 4 + i;
                As[so][k * BM + (a_row ^ swz(k))] = f2tf32(vb[i]);
            }
            const float* w0 = &rb0.x;
            uint32_t* d0 = &Bsm[so][b_kk * BN + (b_n4 ^ swz(b_kk))];
            #pragma unroll
            for (int i = 0; i < 4; i++) d0[i] = f2tf32(w0[i]);
            const float* w1 = &rb1.x;
            uint32_t* d1 = &Bsm[so][(b_kk + 8) * BN + (b_n4 ^ swz(b_kk + 8))];
            #pragma unroll
            for (int i = 0; i < 4; i++) d1[i] = f2tf32(w1[i]);
            __syncthreads();
            st = so;
        }
    }

    // ---- epilogue ----
    #pragma unroll
    for (int mt = 0; mt < 4; mt++) {
        int r1 = row0 + wm * 64 + mt * 16 + gid;
        int r2 = r1 + 8;
        float s1 = 1.0f, s2 = 1.0f;
        if (SCALE_DINV) {
            if (r1 < M) s1 = g_dinv[r1];
            if (r2 < M) s2 = g_dinv[r2];
        }
        #pragma unroll
        for (int nt = 0; nt < 4; nt++) {
            int col = col0 + wn * 32 + nt * 8 + tig * 2;
            if (r1 < M) {
                float2 v = make_float2(acc[mt][nt][0] * s1, acc[mt][nt][1] * s1);
                *reinterpret_cast<float2*>(Cp + (size_t)r1 * NDIM + col) = v;
            }
            if (r2 < M) {
                float2 v = make_float2(acc[mt][nt][2] * s2, acc[mt][nt][3] * s2);
                *reinterpret_cast<float2*>(Cp + (size_t)r2 * NDIM + col) = v;
            }
        }
    }
}

// ---------------- Kernel C: SpMM  Y = f(an @ X)  with pre-scaled X -----------
template<bool RELU_SCALE>
__global__ __launch_bounds__(256)
void k_spmm(const float4* __restrict__ X, float4* __restrict__ Y)
{
    const int sub  = threadIdx.x >> 6;
    const int lane = threadIdx.x & 63;
    const int row  = blockIdx.x * 4 + sub;

    __shared__ int s_cols[4][CAP];
    const int cnt = g_cnt[row];
    {
        const int* __restrict__ cols = g_cols + (size_t)row * CAP;
        for (int k = lane; k < cnt; k += 64) s_cols[sub][k] = cols[k];
    }
    __syncthreads();

    const int* __restrict__ sc = s_cols[sub];
    const int HV = HH / 4;

    float4 a = X[(size_t)row * HV + lane];
    float4 acc = a;

    int k = 0;
    for (; k + 4 <= cnt; k += 4) {
        int j0 = sc[k], j1 = sc[k+1], j2 = sc[k+2], j3 = sc[k+3];
        float4 v0 = X[(size_t)j0 * HV + lane];
        float4 v1 = X[(size_t)j1 * HV + lane];
        float4 v2 = X[(size_t)j2 * HV + lane];
        float4 v3 = X[(size_t)j3 * HV + lane];
        acc.x += (v0.x + v1.x) + (v2.x + v3.x);
        acc.y += (v0.y + v1.y) + (v2.y + v3.y);
        acc.z += (v0.z + v1.z) + (v2.z + v3.z);
        acc.w += (v0.w + v1.w) + (v2.w + v3.w);
    }
    for (; k < cnt; k++) {
        float4 v = X[(size_t)sc[k] * HV + lane];
        acc.x += v.x; acc.y += v.y; acc.z += v.z; acc.w += v.w;
    }

    const float di = g_dinv[row];
    float4 o;
    if (RELU_SCALE) {
        o.x = di * fmaxf(di * acc.x, 0.0f);
        o.y = di * fmaxf(di * acc.y, 0.0f);
        o.z = di * fmaxf(di * acc.z, 0.0f);
        o.w = di * fmaxf(di * acc.w, 0.0f);
    } else {
        o.x = di * acc.x;
        o.y = di * acc.y;
        o.z = di * acc.z;
        o.w = di * acc.w;
    }
    Y[(size_t)row * HV + lane] = o;
}

// ---------------- launch ----------------
extern "C" void kernel_launch(void* const* d_in, const int* in_sizes, int n_in,
                              void* d_out, int out_size)
{
    const float* adj = (const float*)d_in[0];   // [N, N]
    const float* x   = (const float*)d_in[1];   // [N, D]
    const float* W1  = (const float*)d_in[2];   // [D, H]
    const float* Wm  = (const float*)d_in[3];   // [H, O]
    const float* Ws  = (const float*)d_in[4];   // [H, O]
    float* out = (float*)d_out;                 // [2, N, O]

    float* xw; cudaGetSymbolAddress((void**)&xw, g_xw);
    float* h;  cudaGetSymbolAddress((void**)&h,  g_h);
    float* g;  cudaGetSymbolAddress((void**)&g,  g_g);
    int*   cntL; cudaGetSymbolAddress((void**)&cntL, g_cntL);

    const int mtiles = (NN + 127) / 128;        // 79

    // 1. zero counters (memset node), upper-triangle scan, deterministic merge
    cudaMemsetAsync(cntL, 0, NN * sizeof(int));
    k_scan_ut<<<NN, 256>>>(adj);
    k_merge<<<(NN + 7) / 8, 256>>>();

    // 2. u = dinv .* (x @ W1)   [10000,512]@[512,256]
    k_mma<DD, true, false><<<dim3(HH / 128, mtiles), 256>>>(x, W1, nullptr, xw, NN, HH);

    // 3. hs = dinv .* relu(an @ (x@W1))
    k_spmm<true><<<NN / 4, 256>>>((const float4*)xw, (float4*)h);

    // 4. g = an @ h
    k_spmm<false><<<NN / 4, 256>>>((const float4*)h, (float4*)g);

    // 5. z_mean = g @ Wm ; z_log_std = g @ Ws   (grid.x = bsel)
    k_mma<HH, false, true><<<dim3(2, mtiles), 256>>>(g, Wm, Ws, out, NN, OO);
}

// round 7
// speedup vs baseline: 1.1710x; 1.1710x over previous
#include <cuda_runtime.h>
#include <math.h>
#include <stdint.h>

#define NN 10000
#define DD 512
#define HH 256
#define OO 128
#define CAP 128          // final merged neighbor cap per row
#define CAPH 96          // cap per half (upper / lower)
#define LCAP 16          // per-thread local buffer in scan

// ---------------- scratch (static device memory; no allocations) -------------
__device__ int   g_cols [(size_t)NN * CAP];    // merged neighbor lists
__device__ int   g_cnt  [NN];                  // merged nnz per row
__device__ float g_dinv [NN];                  // rsqrt(degree)
__device__ int   g_colsU[(size_t)NN * CAPH];   // upper-tri neighbors (own scan)
__device__ int   g_cntU [NN];
__device__ int   g_colsL[(size_t)NN * CAPH];   // lower-tri neighbors (atomic scatter)
__device__ int   g_cntL [NN];
__device__ float g_xw  [(size_t)NN * HH];      // u  = dinv .* (x @ W1)
__device__ float g_h   [(size_t)NN * HH];      // hs = dinv .* relu(an @ xw)
__device__ float g_g   [(size_t)NN * HH];      // g  = an @ h

// ---------------- Kernel A: upper-triangle scan ------------------------------
__global__ __launch_bounds__(256)
void k_scan_ut(const float* __restrict__ adj)
{
    const int row = blockIdx.x;
    const int tid = threadIdx.x;
    const uint32_t* __restrict__ arow =
        reinterpret_cast<const uint32_t*>(adj + (size_t)row * NN);

    int local[LCAP];
    int lc = 0;

    const int start = row + 1;
    int aligned = (start + 15) & ~15;
    if (aligned > NN) aligned = NN;

    {
        int c = start + tid;
        if (c < aligned && arow[c] != 0u) { local[lc] = c; lc++; }
    }

    const uint4* __restrict__ arow4 = reinterpret_cast<const uint4*>(arow);
    const int base = aligned >> 4;
    const int nch  = NN >> 4;
    for (int t = base + tid; t < nch; t += 256) {
        const uint4* p = arow4 + 4 * t;
        uint4 w0 = p[0], w1 = p[1], w2 = p[2], w3 = p[3];
        uint32_t m = ((w0.x | w0.y) | (w0.z | w0.w))
                   | ((w1.x | w1.y) | (w1.z | w1.w))
                   | ((w2.x | w2.y) | (w2.z | w2.w))
                   | ((w3.x | w3.y) | (w3.z | w3.w));
        if (m != 0u) {
            const int c0 = t << 4;
            #define CHK(w, off) if ((w) != 0u) { if (lc < LCAP) local[lc] = c0 + (off); lc++; }
            CHK(w0.x, 0)  CHK(w0.y, 1)  CHK(w0.z, 2)  CHK(w0.w, 3)
            CHK(w1.x, 4)  CHK(w1.y, 5)  CHK(w1.z, 6)  CHK(w1.w, 7)
            CHK(w2.x, 8)  CHK(w2.y, 9)  CHK(w2.z, 10) CHK(w2.w, 11)
            CHK(w3.x, 12) CHK(w3.y, 13) CHK(w3.z, 14) CHK(w3.w, 15)
            #undef CHK
        }
    }
    if (lc > LCAP) lc = LCAP;

    __shared__ int s_c[256];
    __shared__ int s_off[256];
    __shared__ int s_total;
    s_c[tid] = lc;
    __syncthreads();
    if (tid == 0) {
        int acc = 0;
        #pragma unroll 8
        for (int i = 0; i < 256; i++) { s_off[i] = acc; acc += s_c[i]; }
        s_total = acc;
    }
    __syncthreads();

    int* __restrict__ ucols = g_colsU + (size_t)row * CAPH;
    int pos = s_off[tid];
    for (int i = 0; i < lc; i++) {
        int c = local[i];
        int p = pos + i;
        if (p < CAPH) ucols[p] = c;
        int lp = atomicAdd(&g_cntL[c], 1);
        if (lp < CAPH) g_colsL[(size_t)c * CAPH + lp] = row;
    }
    if (tid == 0) {
        int total = s_total;
        if (total > CAPH) total = CAPH;
        g_cntU[row] = total;
    }
}

// ---------------- Kernel M: merge L (sorted) + U -> g_cols, cnt, dinv --------
__global__ __launch_bounds__(256)
void k_merge()
{
    const int lane = threadIdx.x & 31;
    const int row  = blockIdx.x * 8 + (threadIdx.x >> 5);
    if (row >= NN) return;

    int cntL = g_cntL[row]; if (cntL > CAPH) cntL = CAPH;
    int cntU = g_cntU[row]; if (cntU > CAPH) cntU = CAPH;
    int total = cntL + cntU; if (total > CAP) total = CAP;

    const int* __restrict__ L = g_colsL + (size_t)row * CAPH;
    const int* __restrict__ U = g_colsU + (size_t)row * CAPH;
    int* __restrict__ dst = g_cols + (size_t)row * CAP;

    for (int s = lane; s < cntL; s += 32) {
        int v = L[s];
        int rank = 0;
        for (int j = 0; j < cntL; j++) rank += (L[j] < v) ? 1 : 0;
        if (rank < CAP) dst[rank] = v;
    }
    for (int k = lane; k < cntU; k += 32) {
        int p = cntL + k;
        if (p < CAP) dst[p] = U[k];
    }
    if (lane == 0) {
        g_cnt[row]  = total;
        g_dinv[row] = rsqrtf((float)total + 1.0f);
    }
}

// ---------------- tf32 helpers ----------------
__device__ __forceinline__ uint32_t f2tf32(float x)
{
    uint32_t r;
    asm("cvt.rna.tf32.f32 %0, %1;" : "=r"(r) : "f"(x));
    return r;
}

__device__ __forceinline__ void mma_tf32(float c[4],
    uint32_t a0, uint32_t a1, uint32_t a2, uint32_t a3,
    uint32_t b0, uint32_t b1)
{
    asm volatile(
        "mma.sync.aligned.m16n8k8.row.col.f32.tf32.tf32.f32 "
        "{%0,%1,%2,%3}, {%4,%5,%6,%7}, {%8,%9}, {%0,%1,%2,%3};"
        : "+f"(c[0]), "+f"(c[1]), "+f"(c[2]), "+f"(c[3])
        : "r"(a0), "r"(a1), "r"(a2), "r"(a3), "r"(b0), "r"(b1));
}

__device__ __forceinline__ int swz(int k)
{
    return ((k & 3) ^ ((k >> 2) & 3)) << 3;
}

// ---------------- Kernel B: tf32 tensor-core GEMM  (R4 proven config) -------
// BM=BN=128, BK=16, 128 threads (4 warps, 64x64 warp tiles), double-buffered.
template<int KDIM, bool SCALE_DINV, bool DUAL_B>
__global__ __launch_bounds__(128)
void k_mma(const float* __restrict__ A, const float* __restrict__ Bm,
           const float* __restrict__ Bs2, float* __restrict__ C,
           int M, int NDIM)
{
    const int BM = 128, BN = 128, BK = 16;
    const int NIT = KDIM / BK;
    __shared__ uint32_t As[2][BK * BM];
    __shared__ uint32_t Bsm[2][BK * BN];

    const int tid  = threadIdx.x;
    const int lane = tid & 31;
    const int warp = tid >> 5;
    const int wm   = warp >> 1;
    const int wn   = warp & 1;
    const int gid  = lane >> 2;
    const int tig  = lane & 3;

    const int row0 = blockIdx.y * BM;
    const float* __restrict__ B = DUAL_B ? (blockIdx.x ? Bs2 : Bm) : Bm;
    const int col0 = DUAL_B ? 0 : blockIdx.x * BN;
    float* __restrict__ Cp = DUAL_B ? (C + (size_t)blockIdx.x * (size_t)M * NDIM) : C;

    const int a_m  = tid >> 2;
    const int a_kq = tid & 3;
    const int b_k  = tid >> 3;
    const int b_n4 = (tid & 7) * 4;

    float acc[4][8][4];
    #pragma unroll
    for (int mt = 0; mt < 4; mt++)
        #pragma unroll
        for (int nt = 0; nt < 8; nt++)
            #pragma unroll
            for (int i = 0; i < 4; i++) acc[mt][nt][i] = 0.0f;

    float4 ra[4], rb[4];

    #pragma unroll
    for (int j = 0; j < 4; j++) {
        int m = a_m + 32 * j;
        int gr = row0 + m;
        ra[j] = (gr < M)
            ? *reinterpret_cast<const float4*>(A + (size_t)gr * KDIM + a_kq * 4)
            : make_float4(0.f, 0.f, 0.f, 0.f);
        rb[j] = *reinterpret_cast<const float4*>(B + (size_t)b_k * NDIM + col0 + b_n4 + 32 * j);
    }
    {
        #pragma unroll
        for (int j = 0; j < 4; j++) {
            int m = a_m + 32 * j;
            const float* v = &ra[j].x;
            #pragma unroll
            for (int i = 0; i < 4; i++) {
                int k = a_kq * 4 + i;
                As[0][k * BM + (m ^ swz(k))] = f2tf32(v[i]);
            }
            int n = b_n4 + 32 * j;
            const float* w = &rb[j].x;
            uint32_t* dst = &Bsm[0][b_k * BN + (n ^ swz(b_k))];
            #pragma unroll
            for (int i = 0; i < 4; i++) dst[i] = f2tf32(w[i]);
        }
    }
    __syncthreads();

    int st = 0;
    for (int it = 0; it < NIT; ++it) {
        if (it + 1 < NIT) {
            int k0 = (it + 1) * BK;
            #pragma unroll
            for (int j = 0; j < 4; j++) {
                int m = a_m + 32 * j;
                int gr = row0 + m;
                ra[j] = (gr < M)
                    ? *reinterpret_cast<const float4*>(A + (size_t)gr * KDIM + k0 + a_kq * 4)
                    : make_float4(0.f, 0.f, 0.f, 0.f);
                rb[j] = *reinterpret_cast<const float4*>(B + (size_t)(k0 + b_k) * NDIM + col0 + b_n4 + 32 * j);
            }
        }

        #pragma unroll
        for (int ks = 0; ks < BK; ks += 8) {
            const int k1 = ks + tig;
            const int k2 = ks + tig + 4;
            const int sx1 = swz(k1);
            const int sx2 = swz(k2);

            uint32_t af[4][4];
            #pragma unroll
            for (int mt = 0; mt < 4; mt++) {
                int r1 = wm * 64 + mt * 16 + gid;
                af[mt][0] = As[st][k1 * BM + (r1 ^ sx1)];
                af[mt][1] = As[st][k1 * BM + ((r1 + 8) ^ sx1)];
                af[mt][2] = As[st][k2 * BM + (r1 ^ sx2)];
                af[mt][3] = As[st][k2 * BM + ((r1 + 8) ^ sx2)];
            }
            uint32_t bf[8][2];
            #pragma unroll
            for (int nt = 0; nt < 8; nt++) {
                int cn = wn * 64 + nt * 8 + gid;
                bf[nt][0] = Bsm[st][k1 * BN + (cn ^ sx1)];
                bf[nt][1] = Bsm[st][k2 * BN + (cn ^ sx2)];
            }
            #pragma unroll
            for (int mt = 0; mt < 4; mt++)
                #pragma unroll
                for (int nt = 0; nt < 8; nt++)
                    mma_tf32(acc[mt][nt], af[mt][0], af[mt][1], af[mt][2], af[mt][3],
                             bf[nt][0], bf[nt][1]);
        }

        if (it + 1 < NIT) {
            int so = st ^ 1;
            #pragma unroll
            for (int j = 0; j < 4; j++) {
                int m = a_m + 32 * j;
                const float* v = &ra[j].x;
                #pragma unroll
                for (int i = 0; i < 4; i++) {
                    int k = a_kq * 4 + i;
                    As[so][k * BM + (m ^ swz(k))] = f2tf32(v[i]);
                }
                int n = b_n4 + 32 * j;
                const float* w = &rb[j].x;
                uint32_t* dst = &Bsm[so][b_k * BN + (n ^ swz(b_k))];
                #pragma unroll
                for (int i = 0; i < 4; i++) dst[i] = f2tf32(w[i]);
            }
            __syncthreads();
            st = so;
        }
    }

    #pragma unroll
    for (int mt = 0; mt < 4; mt++) {
        int r1 = row0 + wm * 64 + mt * 16 + gid;
        int r2 = r1 + 8;
        float s1 = 1.0f, s2 = 1.0f;
        if (SCALE_DINV) {
            if (r1 < M) s1 = g_dinv[r1];
            if (r2 < M) s2 = g_dinv[r2];
        }
        #pragma unroll
        for (int nt = 0; nt < 8; nt++) {
            int col = col0 + wn * 64 + nt * 8 + tig * 2;
            if (r1 < M) {
                float2 v = make_float2(acc[mt][nt][0] * s1, acc[mt][nt][1] * s1);
                *reinterpret_cast<float2*>(Cp + (size_t)r1 * NDIM + col) = v;
            }
            if (r2 < M) {
                float2 v = make_float2(acc[mt][nt][2] * s2, acc[mt][nt][3] * s2);
                *reinterpret_cast<float2*>(Cp + (size_t)r2 * NDIM + col) = v;
            }
        }
    }
}

// ---------------- Kernel C: SpMM  Y = f(an @ X), warp-per-row ----------------
// 8 rows/block, 32 lanes/row, each lane owns float4 columns lane and lane+32.
// Inner loop: 4 neighbors -> 8 independent LDG.128 in flight. Pure adds.
__device__ __forceinline__ void f4add(float4& a, const float4& b)
{
    a.x += b.x; a.y += b.y; a.z += b.z; a.w += b.w;
}

template<bool RELU_SCALE>
__global__ __launch_bounds__(256)
void k_spmm(const float4* __restrict__ X, float4* __restrict__ Y)
{
    const int sub  = threadIdx.x >> 5;              // 0..7 row within block
    const int lane = threadIdx.x & 31;
    const int row  = blockIdx.x * 8 + sub;

    __shared__ int s_cols[8][CAP];
    const int cnt = g_cnt[row];
    {
        const int* __restrict__ cols = g_cols + (size_t)row * CAP;
        for (int k = lane; k < cnt; k += 32) s_cols[sub][k] = cols[k];
    }
    __syncwarp();                                   // row is private to this warp

    const int* __restrict__ sc = s_cols[sub];
    const int HV = HH / 4;                          // 64 float4 per row

    const float4* __restrict__ Xr = X + (size_t)row * HV;
    float4 acc0 = Xr[lane];                         // self term
    float4 acc1 = Xr[lane + 32];

    int k = 0;
    for (; k + 4 <= cnt; k += 4) {
        const float4* p0 = X + (size_t)sc[k]     * HV;
        const float4* p1 = X + (size_t)sc[k + 1] * HV;
        const float4* p2 = X + (size_t)sc[k + 2] * HV;
        const float4* p3 = X + (size_t)sc[k + 3] * HV;
        float4 a0 = p0[lane],      b0 = p1[lane],      c0 = p2[lane],      d0 = p3[lane];
        float4 a1 = p0[lane + 32], b1 = p1[lane + 32], c1 = p2[lane + 32], d1 = p3[lane + 32];
        f4add(a0, b0); f4add(c0, d0); f4add(a0, c0); f4add(acc0, a0);
        f4add(a1, b1); f4add(c1, d1); f4add(a1, c1); f4add(acc1, a1);
    }
    for (; k < cnt; k++) {
        const float4* p = X + (size_t)sc[k] * HV;
        float4 v0 = p[lane];
        float4 v1 = p[lane + 32];
        f4add(acc0, v0);
        f4add(acc1, v1);
    }

    const float di = g_dinv[row];
    float4 o0, o1;
    if (RELU_SCALE) {
        o0.x = di * fmaxf(di * acc0.x, 0.0f);
        o0.y = di * fmaxf(di * acc0.y, 0.0f);
        o0.z = di * fmaxf(di * acc0.z, 0.0f);
        o0.w = di * fmaxf(di * acc0.w, 0.0f);
        o1.x = di * fmaxf(di * acc1.x, 0.0f);
        o1.y = di * fmaxf(di * acc1.y, 0.0f);
        o1.z = di * fmaxf(di * acc1.z, 0.0f);
        o1.w = di * fmaxf(di * acc1.w, 0.0f);
    } else {
        o0.x = di * acc0.x; o0.y = di * acc0.y; o0.z = di * acc0.z; o0.w = di * acc0.w;
        o1.x = di * acc1.x; o1.y = di * acc1.y; o1.z = di * acc1.z; o1.w = di * acc1.w;
    }
    float4* __restrict__ Yr = Y + (size_t)row * HV;
    Yr[lane]      = o0;
    Yr[lane + 32] = o1;
}

// ---------------- launch ----------------
extern "C" void kernel_launch(void* const* d_in, const int* in_sizes, int n_in,
                              void* d_out, int out_size)
{
    const float* adj = (const float*)d_in[0];   // [N, N]
    const float* x   = (const float*)d_in[1];   // [N, D]
    const float* W1  = (const float*)d_in[2];   // [D, H]
    const float* Wm  = (const float*)d_in[3];   // [H, O]
    const float* Ws  = (const float*)d_in[4];   // [H, O]
    float* out = (float*)d_out;                 // [2, N, O]

    float* xw; cudaGetSymbolAddress((void**)&xw, g_xw);
    float* h;  cudaGetSymbolAddress((void**)&h,  g_h);
    float* g;  cudaGetSymbolAddress((void**)&g,  g_g);
    int*   cntL; cudaGetSymbolAddress((void**)&cntL, g_cntL);

    const int mtiles = (NN + 127) / 128;        // 79

    // 1. zero counters (memset node), upper-triangle scan, deterministic merge
    cudaMemsetAsync(cntL, 0, NN * sizeof(int));
    k_scan_ut<<<NN, 256>>>(adj);
    k_merge<<<(NN + 7) / 8, 256>>>();

    // 2. u = dinv .* (x @ W1)   [10000,512]@[512,256]
    k_mma<DD, true, false><<<dim3(HH / 128, mtiles), 128>>>(x, W1, nullptr, xw, NN, HH);

    // 3. hs = dinv .* relu(an @ (x@W1))
    k_spmm<true><<<NN / 8, 256>>>((const float4*)xw, (float4*)h);

    // 4. g = an @ h
    k_spmm<false><<<NN / 8, 256>>>((const float4*)h, (float4*)g);

    // 5. z_mean = g @ Wm ; z_log_std = g @ Ws
    k_mma<HH, false, true><<<dim3(2, mtiles), 128>>>(g, Wm, Ws, out, NN, OO);
}

// round 8
// speedup vs baseline: 1.4557x; 1.2431x over previous
#include <cuda_runtime.h>
#include <math.h>
#include <stdint.h>

#define NN 10000
#define DD 512
#define HH 256
#define OO 128
#define CAP 128          // final merged neighbor cap per row
#define CAPH 96          // cap per half (upper / lower)
#define LCAP 16          // per-lane local buffer in scan

// ---------------- scratch (static device memory; no allocations) -------------
__device__ int   g_cols [(size_t)NN * CAP];    // merged neighbor lists
__device__ int   g_cnt  [NN];                  // merged nnz per row
__device__ float g_dinv [NN];                  // rsqrt(degree)
__device__ int   g_colsU[(size_t)NN * CAPH];   // upper-tri neighbors (own scan)
__device__ int   g_cntU [NN];
__device__ int   g_colsL[(size_t)NN * CAPH];   // lower-tri neighbors (atomic scatter)
__device__ int   g_cntL [NN];
__device__ float g_xw  [(size_t)NN * HH];      // u  = dinv .* (x @ W1)
__device__ float g_h   [(size_t)NN * HH];      // hs = dinv .* relu(an @ xw)
__device__ float g_g   [(size_t)NN * HH];      // g  = an @ h

// ---------------- Kernel A: upper-triangle scan, warp-per-row ----------------
// 8 rows per 256-thread block, one warp per row. No shared memory, no
// __syncthreads: per-warp exclusive prefix scan via shfl. Deterministic
// thread-major ordering of the U list (same scheme as before).
__global__ __launch_bounds__(256)
void k_scan_ut(const float* __restrict__ adj)
{
    const int lane = threadIdx.x & 31;
    const int row  = blockIdx.x * 8 + (threadIdx.x >> 5);
    const uint32_t* __restrict__ arow =
        reinterpret_cast<const uint32_t*>(adj + (size_t)row * NN);

    int local[LCAP];
    int lc = 0;

    const int start = row + 1;
    int aligned = (start + 15) & ~15;
    if (aligned > NN) aligned = NN;

    // head (< 16 elements): one column per lane
    {
        int c = start + lane;
        if (c < aligned && arow[c] != 0u) { local[lc] = c; lc++; }
    }

    // body: 64B chunks (16 words), OR-tree rejection
    const uint4* __restrict__ arow4 = reinterpret_cast<const uint4*>(arow);
    const int base = aligned >> 4;
    const int nch  = NN >> 4;          // 625
    for (int t = base + lane; t < nch; t += 32) {
        const uint4* p = arow4 + 4 * t;
        uint4 w0 = p[0], w1 = p[1], w2 = p[2], w3 = p[3];
        uint32_t m = ((w0.x | w0.y) | (w0.z | w0.w))
                   | ((w1.x | w1.y) | (w1.z | w1.w))
                   | ((w2.x | w2.y) | (w2.z | w2.w))
                   | ((w3.x | w3.y) | (w3.z | w3.w));
        if (m != 0u) {
            const int c0 = t << 4;
            #define CHK(w, off) if ((w) != 0u) { if (lc < LCAP) local[lc] = c0 + (off); lc++; }
            CHK(w0.x, 0)  CHK(w0.y, 1)  CHK(w0.z, 2)  CHK(w0.w, 3)
            CHK(w1.x, 4)  CHK(w1.y, 5)  CHK(w1.z, 6)  CHK(w1.w, 7)
            CHK(w2.x, 8)  CHK(w2.y, 9)  CHK(w2.z, 10) CHK(w2.w, 11)
            CHK(w3.x, 12) CHK(w3.y, 13) CHK(w3.z, 14) CHK(w3.w, 15)
            #undef CHK
        }
    }
    if (lc > LCAP) lc = LCAP;

    // warp-level exclusive prefix scan of lc
    int inc = lc;
    #pragma unroll
    for (int d = 1; d < 32; d <<= 1) {
        int n = __shfl_up_sync(0xffffffffu, inc, d);
        if (lane >= d) inc += n;
    }
    const int pos   = inc - lc;                       // exclusive offset
    const int total = __shfl_sync(0xffffffffu, inc, 31);

    // write U list (deterministic lane-major order) + scatter into L lists
    int* __restrict__ ucols = g_colsU + (size_t)row * CAPH;
    for (int i = 0; i < lc; i++) {
        int c = local[i];
        int p = pos + i;
        if (p < CAPH) ucols[p] = c;
        int lp = atomicAdd(&g_cntL[c], 1);
        if (lp < CAPH) g_colsL[(size_t)c * CAPH + lp] = row;
    }
    if (lane == 0) {
        int t = total;
        if (t > CAPH) t = CAPH;
        g_cntU[row] = t;
    }
}

// ---------------- Kernel M: merge L (sorted) + U -> g_cols, cnt, dinv --------
__global__ __launch_bounds__(256)
void k_merge()
{
    const int lane = threadIdx.x & 31;
    const int row  = blockIdx.x * 8 + (threadIdx.x >> 5);
    if (row >= NN) return;

    int cntL = g_cntL[row]; if (cntL > CAPH) cntL = CAPH;
    int cntU = g_cntU[row]; if (cntU > CAPH) cntU = CAPH;
    int total = cntL + cntU; if (total > CAP) total = CAP;

    const int* __restrict__ L = g_colsL + (size_t)row * CAPH;
    const int* __restrict__ U = g_colsU + (size_t)row * CAPH;
    int* __restrict__ dst = g_cols + (size_t)row * CAP;

    for (int s = lane; s < cntL; s += 32) {
        int v = L[s];
        int rank = 0;
        for (int j = 0; j < cntL; j++) rank += (L[j] < v) ? 1 : 0;
        if (rank < CAP) dst[rank] = v;
    }
    for (int k = lane; k < cntU; k += 32) {
        int p = cntL + k;
        if (p < CAP) dst[p] = U[k];
    }
    if (lane == 0) {
        g_cnt[row]  = total;
        g_dinv[row] = rsqrtf((float)total + 1.0f);
    }
}

// ---------------- tf32 helpers ----------------
__device__ __forceinline__ uint32_t f2tf32(float x)
{
    uint32_t r;
    asm("cvt.rna.tf32.f32 %0, %1;" : "=r"(r) : "f"(x));
    return r;
}

__device__ __forceinline__ void mma_tf32(float c[4],
    uint32_t a0, uint32_t a1, uint32_t a2, uint32_t a3,
    uint32_t b0, uint32_t b1)
{
    asm volatile(
        "mma.sync.aligned.m16n8k8.row.col.f32.tf32.tf32.f32 "
        "{%0,%1,%2,%3}, {%4,%5,%6,%7}, {%8,%9}, {%0,%1,%2,%3};"
        : "+f"(c[0]), "+f"(c[1]), "+f"(c[2]), "+f"(c[3])
        : "r"(a0), "r"(a1), "r"(a2), "r"(a3), "r"(b0), "r"(b1));
}

__device__ __forceinline__ int swz(int k)
{
    return ((k & 3) ^ ((k >> 2) & 3)) << 3;
}

// ---------------- Kernel B: tf32 tensor-core GEMM  (R4 proven config) -------
// BM=BN=128, BK=16, 128 threads (4 warps, 64x64 warp tiles), double-buffered.
template<int KDIM, bool SCALE_DINV, bool DUAL_B>
__global__ __launch_bounds__(128)
void k_mma(const float* __restrict__ A, const float* __restrict__ Bm,
           const float* __restrict__ Bs2, float* __restrict__ C,
           int M, int NDIM)
{
    const int BM = 128, BN = 128, BK = 16;
    const int NIT = KDIM / BK;
    __shared__ uint32_t As[2][BK * BM];
    __shared__ uint32_t Bsm[2][BK * BN];

    const int tid  = threadIdx.x;
    const int lane = tid & 31;
    const int warp = tid >> 5;
    const int wm   = warp >> 1;
    const int wn   = warp & 1;
    const int gid  = lane >> 2;
    const int tig  = lane & 3;

    const int row0 = blockIdx.y * BM;
    const float* __restrict__ B = DUAL_B ? (blockIdx.x ? Bs2 : Bm) : Bm;
    const int col0 = DUAL_B ? 0 : blockIdx.x * BN;
    float* __restrict__ Cp = DUAL_B ? (C + (size_t)blockIdx.x * (size_t)M * NDIM) : C;

    const int a_m  = tid >> 2;
    const int a_kq = tid & 3;
    const int b_k  = tid >> 3;
    const int b_n4 = (tid & 7) * 4;

    float acc[4][8][4];
    #pragma unroll
    for (int mt = 0; mt < 4; mt++)
        #pragma unroll
        for (int nt = 0; nt < 8; nt++)
            #pragma unroll
            for (int i = 0; i < 4; i++) acc[mt][nt][i] = 0.0f;

    float4 ra[4], rb[4];

    #pragma unroll
    for (int j = 0; j < 4; j++) {
        int m = a_m + 32 * j;
        int gr = row0 + m;
        ra[j] = (gr < M)
            ? *reinterpret_cast<const float4*>(A + (size_t)gr * KDIM + a_kq * 4)
            : make_float4(0.f, 0.f, 0.f, 0.f);
        rb[j] = *reinterpret_cast<const float4*>(B + (size_t)b_k * NDIM + col0 + b_n4 + 32 * j);
    }
    {
        #pragma unroll
        for (int j = 0; j < 4; j++) {
            int m = a_m + 32 * j;
            const float* v = &ra[j].x;
            #pragma unroll
            for (int i = 0; i < 4; i++) {
                int k = a_kq * 4 + i;
                As[0][k * BM + (m ^ swz(k))] = f2tf32(v[i]);
            }
            int n = b_n4 + 32 * j;
            const float* w = &rb[j].x;
            uint32_t* dst = &Bsm[0][b_k * BN + (n ^ swz(b_k))];
            #pragma unroll
            for (int i = 0; i < 4; i++) dst[i] = f2tf32(w[i]);
        }
    }
    __syncthreads();

    int st = 0;
    for (int it = 0; it < NIT; ++it) {
        if (it + 1 < NIT) {
            int k0 = (it + 1) * BK;
            #pragma unroll
            for (int j = 0; j < 4; j++) {
                int m = a_m + 32 * j;
                int gr = row0 + m;
                ra[j] = (gr < M)
                    ? *reinterpret_cast<const float4*>(A + (size_t)gr * KDIM + k0 + a_kq * 4)
                    : make_float4(0.f, 0.f, 0.f, 0.f);
                rb[j] = *reinterpret_cast<const float4*>(B + (size_t)(k0 + b_k) * NDIM + col0 + b_n4 + 32 * j);
            }
        }

        #pragma unroll
        for (int ks = 0; ks < BK; ks += 8) {
            const int k1 = ks + tig;
            const int k2 = ks + tig + 4;
            const int sx1 = swz(k1);
            const int sx2 = swz(k2);

            uint32_t af[4][4];
            #pragma unroll
            for (int mt = 0; mt < 4; mt++) {
                int r1 = wm * 64 + mt * 16 + gid;
                af[mt][0] = As[st][k1 * BM + (r1 ^ sx1)];
                af[mt][1] = As[st][k1 * BM + ((r1 + 8) ^ sx1)];
                af[mt][2] = As[st][k2 * BM + (r1 ^ sx2)];
                af[mt][3] = As[st][k2 * BM + ((r1 + 8) ^ sx2)];
            }
            uint32_t bf[8][2];
            #pragma unroll
            for (int nt = 0; nt < 8; nt++) {
                int cn = wn * 64 + nt * 8 + gid;
                bf[nt][0] = Bsm[st][k1 * BN + (cn ^ sx1)];
                bf[nt][1] = Bsm[st][k2 * BN + (cn ^ sx2)];
            }
            #pragma unroll
            for (int mt = 0; mt < 4; mt++)
                #pragma unroll
                for (int nt = 0; nt < 8; nt++)
                    mma_tf32(acc[mt][nt], af[mt][0], af[mt][1], af[mt][2], af[mt][3],
                             bf[nt][0], bf[nt][1]);
        }

        if (it + 1 < NIT) {
            int so = st ^ 1;
            #pragma unroll
            for (int j = 0; j < 4; j++) {
                int m = a_m + 32 * j;
                const float* v = &ra[j].x;
                #pragma unroll
                for (int i = 0; i < 4; i++) {
                    int k = a_kq * 4 + i;
                    As[so][k * BM + (m ^ swz(k))] = f2tf32(v[i]);
                }
                int n = b_n4 + 32 * j;
                const float* w = &rb[j].x;
                uint32_t* dst = &Bsm[so][b_k * BN + (n ^ swz(b_k))];
                #pragma unroll
                for (int i = 0; i < 4; i++) dst[i] = f2tf32(w[i]);
            }
            __syncthreads();
            st = so;
        }
    }

    #pragma unroll
    for (int mt = 0; mt < 4; mt++) {
        int r1 = row0 + wm * 64 + mt * 16 + gid;
        int r2 = r1 + 8;
        float s1 = 1.0f, s2 = 1.0f;
        if (SCALE_DINV) {
            if (r1 < M) s1 = g_dinv[r1];
            if (r2 < M) s2 = g_dinv[r2];
        }
        #pragma unroll
        for (int nt = 0; nt < 8; nt++) {
            int col = col0 + wn * 64 + nt * 8 + tig * 2;
            if (r1 < M) {
                float2 v = make_float2(acc[mt][nt][0] * s1, acc[mt][nt][1] * s1);
                *reinterpret_cast<float2*>(Cp + (size_t)r1 * NDIM + col) = v;
            }
            if (r2 < M) {
                float2 v = make_float2(acc[mt][nt][2] * s2, acc[mt][nt][3] * s2);
                *reinterpret_cast<float2*>(Cp + (size_t)r2 * NDIM + col) = v;
            }
        }
    }
}

// ---------------- Kernel C: SpMM  Y = f(an @ X)  (R4 proven config) ----------
template<bool RELU_SCALE>
__global__ __launch_bounds__(256)
void k_spmm(const float4* __restrict__ X, float4* __restrict__ Y)
{
    const int sub  = threadIdx.x >> 6;
    const int lane = threadIdx.x & 63;
    const int row  = blockIdx.x * 4 + sub;

    __shared__ int s_cols[4][CAP];
    const int cnt = g_cnt[row];
    {
        const int* __restrict__ cols = g_cols + (size_t)row * CAP;
        for (int k = lane; k < cnt; k += 64) s_cols[sub][k] = cols[k];
    }
    __syncthreads();

    const int* __restrict__ sc = s_cols[sub];
    const int HV = HH / 4;

    float4 a = X[(size_t)row * HV + lane];
    float4 acc = a;

    int k = 0;
    for (; k + 4 <= cnt; k += 4) {
        int j0 = sc[k], j1 = sc[k+1], j2 = sc[k+2], j3 = sc[k+3];
        float4 v0 = X[(size_t)j0 * HV + lane];
        float4 v1 = X[(size_t)j1 * HV + lane];
        float4 v2 = X[(size_t)j2 * HV + lane];
        float4 v3 = X[(size_t)j3 * HV + lane];
        acc.x += (v0.x + v1.x) + (v2.x + v3.x);
        acc.y += (v0.y + v1.y) + (v2.y + v3.y);
        acc.z += (v0.z + v1.z) + (v2.z + v3.z);
        acc.w += (v0.w + v1.w) + (v2.w + v3.w);
    }
    for (; k < cnt; k++) {
        float4 v = X[(size_t)sc[k] * HV + lane];
        acc.x += v.x; acc.y += v.y; acc.z += v.z; acc.w += v.w;
    }

    const float di = g_dinv[row];
    float4 o;
    if (RELU_SCALE) {
        o.x = di * fmaxf(di * acc.x, 0.0f);
        o.y = di * fmaxf(di * acc.y, 0.0f);
        o.z = di * fmaxf(di * acc.z, 0.0f);
        o.w = di * fmaxf(di * acc.w, 0.0f);
    } else {
        o.x = di * acc.x;
        o.y = di * acc.y;
        o.z = di * acc.z;
        o.w = di * acc.w;
    }
    Y[(size_t)row * HV + lane] = o;
}

// ---------------- launch ----------------
extern "C" void kernel_launch(void* const* d_in, const int* in_sizes, int n_in,
                              void* d_out, int out_size)
{
    const float* adj = (const float*)d_in[0];   // [N, N]
    const float* x   = (const float*)d_in[1];   // [N, D]
    const float* W1  = (const float*)d_in[2];   // [D, H]
    const float* Wm  = (const float*)d_in[3];   // [H, O]
    const float* Ws  = (const float*)d_in[4];   // [H, O]
    float* out = (float*)d_out;                 // [2, N, O]

    float* xw; cudaGetSymbolAddress((void**)&xw, g_xw);
    float* h;  cudaGetSymbolAddress((void**)&h,  g_h);
    float* g;  cudaGetSymbolAddress((void**)&g,  g_g);
    int*   cntL; cudaGetSymbolAddress((void**)&cntL, g_cntL);

    const int mtiles = (NN + 127) / 128;        // 79

    // 1. zero counters (memset node), warp-per-row UT scan, deterministic merge
    cudaMemsetAsync(cntL, 0, NN * sizeof(int));
    k_scan_ut<<<NN / 8, 256>>>(adj);
    k_merge<<<(NN + 7) / 8, 256>>>();

    // 2. u = dinv .* (x @ W1)   [10000,512]@[512,256]
    k_mma<DD, true, false><<<dim3(HH / 128, mtiles), 128>>>(x, W1, nullptr, xw, NN, HH);

    // 3. hs = dinv .* relu(an @ (x@W1))
    k_spmm<true><<<NN / 4, 256>>>((const float4*)xw, (float4*)h);

    // 4. g = an @ h
    k_spmm<false><<<NN / 4, 256>>>((const float4*)h, (float4*)g);

    // 5. z_mean = g @ Wm ; z_log_std = g @ Ws
    k_mma<HH, false, true><<<dim3(2, mtiles), 128>>>(g, Wm, Ws, out, NN, OO);
}

// round 9
// speedup vs baseline: 1.5682x; 1.0773x over previous
#include <cuda_runtime.h>
#include <cuda_fp16.h>
#include <math.h>
#include <stdint.h>

#define NN 10000
#define DD 512
#define HH 256
#define OO 128
#define CAP 128          // final merged neighbor cap per row
#define CAPH 96          // cap per half (upper / lower)
#define LCAP 16          // per-lane local buffer in scan

// ---------------- scratch (static device memory; no allocations) -------------
__device__ int    g_cols [(size_t)NN * CAP];    // merged neighbor lists
__device__ int    g_cnt  [NN];                  // merged nnz per row
__device__ float  g_dinv [NN];                  // rsqrt(degree)
__device__ int    g_colsU[(size_t)NN * CAPH];   // upper-tri neighbors (own scan)
__device__ int    g_cntU [NN];
__device__ int    g_colsL[(size_t)NN * CAPH];   // lower-tri neighbors (atomic scatter)
__device__ int    g_cntL [NN];
__device__ __half g_xw  [(size_t)NN * HH];      // u  = dinv .* (x @ W1), fp16
__device__ __half g_h   [(size_t)NN * HH];      // hs = dinv .* relu(an @ xw), fp16
__device__ float  g_g   [(size_t)NN * HH];      // g  = an @ h, fp32

// ---------------- Kernel A: upper-triangle scan, warp-per-row ----------------
__global__ __launch_bounds__(256)
void k_scan_ut(const float* __restrict__ adj)
{
    const int lane = threadIdx.x & 31;
    const int row  = blockIdx.x * 8 + (threadIdx.x >> 5);
    const uint32_t* __restrict__ arow =
        reinterpret_cast<const uint32_t*>(adj + (size_t)row * NN);

    int local[LCAP];
    int lc = 0;

    const int start = row + 1;
    int aligned = (start + 15) & ~15;
    if (aligned > NN) aligned = NN;

    {
        int c = start + lane;
        if (c < aligned && arow[c] != 0u) { local[lc] = c; lc++; }
    }

    const uint4* __restrict__ arow4 = reinterpret_cast<const uint4*>(arow);
    const int base = aligned >> 4;
    const int nch  = NN >> 4;
    for (int t = base + lane; t < nch; t += 32) {
        const uint4* p = arow4 + 4 * t;
        uint4 w0 = p[0], w1 = p[1], w2 = p[2], w3 = p[3];
        uint32_t m = ((w0.x | w0.y) | (w0.z | w0.w))
                   | ((w1.x | w1.y) | (w1.z | w1.w))
                   | ((w2.x | w2.y) | (w2.z | w2.w))
                   | ((w3.x | w3.y) | (w3.z | w3.w));
        if (m != 0u) {
            const int c0 = t << 4;
            #define CHK(w, off) if ((w) != 0u) { if (lc < LCAP) local[lc] = c0 + (off); lc++; }
            CHK(w0.x, 0)  CHK(w0.y, 1)  CHK(w0.z, 2)  CHK(w0.w, 3)
            CHK(w1.x, 4)  CHK(w1.y, 5)  CHK(w1.z, 6)  CHK(w1.w, 7)
            CHK(w2.x, 8)  CHK(w2.y, 9)  CHK(w2.z, 10) CHK(w2.w, 11)
            CHK(w3.x, 12) CHK(w3.y, 13) CHK(w3.z, 14) CHK(w3.w, 15)
            #undef CHK
        }
    }
    if (lc > LCAP) lc = LCAP;

    int inc = lc;
    #pragma unroll
    for (int d = 1; d < 32; d <<= 1) {
        int n = __shfl_up_sync(0xffffffffu, inc, d);
        if (lane >= d) inc += n;
    }
    const int pos   = inc - lc;
    const int total = __shfl_sync(0xffffffffu, inc, 31);

    int* __restrict__ ucols = g_colsU + (size_t)row * CAPH;
    for (int i = 0; i < lc; i++) {
        int c = local[i];
        int p = pos + i;
        if (p < CAPH) ucols[p] = c;
        int lp = atomicAdd(&g_cntL[c], 1);
        if (lp < CAPH) g_colsL[(size_t)c * CAPH + lp] = row;
    }
    if (lane == 0) {
        int t = total;
        if (t > CAPH) t = CAPH;
        g_cntU[row] = t;
    }
}

// ---------------- Kernel M: merge L (sorted) + U -> g_cols, cnt, dinv --------
__global__ __launch_bounds__(256)
void k_merge()
{
    const int lane = threadIdx.x & 31;
    const int row  = blockIdx.x * 8 + (threadIdx.x >> 5);
    if (row >= NN) return;

    int cntL = g_cntL[row]; if (cntL > CAPH) cntL = CAPH;
    int cntU = g_cntU[row]; if (cntU > CAPH) cntU = CAPH;
    int total = cntL + cntU; if (total > CAP) total = CAP;

    const int* __restrict__ L = g_colsL + (size_t)row * CAPH;
    const int* __restrict__ U = g_colsU + (size_t)row * CAPH;
    int* __restrict__ dst = g_cols + (size_t)row * CAP;

    for (int s = lane; s < cntL; s += 32) {
        int v = L[s];
        int rank = 0;
        for (int j = 0; j < cntL; j++) rank += (L[j] < v) ? 1 : 0;
        if (rank < CAP) dst[rank] = v;
    }
    for (int k = lane; k < cntU; k += 32) {
        int p = cntL + k;
        if (p < CAP) dst[p] = U[k];
    }
    if (lane == 0) {
        g_cnt[row]  = total;
        g_dinv[row] = rsqrtf((float)total + 1.0f);
    }
}

// ---------------- tf32 helpers ----------------
__device__ __forceinline__ uint32_t f2tf32(float x)
{
    uint32_t r;
    asm("cvt.rna.tf32.f32 %0, %1;" : "=r"(r) : "f"(x));
    return r;
}

__device__ __forceinline__ void mma_tf32(float c[4],
    uint32_t a0, uint32_t a1, uint32_t a2, uint32_t a3,
    uint32_t b0, uint32_t b1)
{
    asm volatile(
        "mma.sync.aligned.m16n8k8.row.col.f32.tf32.tf32.f32 "
        "{%0,%1,%2,%3}, {%4,%5,%6,%7}, {%8,%9}, {%0,%1,%2,%3};"
        : "+f"(c[0]), "+f"(c[1]), "+f"(c[2]), "+f"(c[3])
        : "r"(a0), "r"(a1), "r"(a2), "r"(a3), "r"(b0), "r"(b1));
}

__device__ __forceinline__ int swz(int k)
{
    return ((k & 3) ^ ((k >> 2) & 3)) << 3;
}

// ---------------- Kernel B: tf32 tensor-core GEMM  (R4 proven config) -------
// BM=BN=128, BK=16, 128 threads (4 warps, 64x64 warp tiles), double-buffered.
// OUT_HALF: write C as fp16 (__half2 pairs) instead of fp32.
template<int KDIM, bool SCALE_DINV, bool DUAL_B, bool OUT_HALF>
__global__ __launch_bounds__(128)
void k_mma(const float* __restrict__ A, const float* __restrict__ Bm,
           const float* __restrict__ Bs2, void* __restrict__ Cv,
           int M, int NDIM)
{
    const int BM = 128, BN = 128, BK = 16;
    const int NIT = KDIM / BK;
    __shared__ uint32_t As[2][BK * BM];
    __shared__ uint32_t Bsm[2][BK * BN];

    const int tid  = threadIdx.x;
    const int lane = tid & 31;
    const int warp = tid >> 5;
    const int wm   = warp >> 1;
    const int wn   = warp & 1;
    const int gid  = lane >> 2;
    const int tig  = lane & 3;

    const int row0 = blockIdx.y * BM;
    const float* __restrict__ B = DUAL_B ? (blockIdx.x ? Bs2 : Bm) : Bm;
    const int col0 = DUAL_B ? 0 : blockIdx.x * BN;
    const size_t coff = DUAL_B ? (size_t)blockIdx.x * (size_t)M * NDIM : 0;

    const int a_m  = tid >> 2;
    const int a_kq = tid & 3;
    const int b_k  = tid >> 3;
    const int b_n4 = (tid & 7) * 4;

    float acc[4][8][4];
    #pragma unroll
    for (int mt = 0; mt < 4; mt++)
        #pragma unroll
        for (int nt = 0; nt < 8; nt++)
            #pragma unroll
            for (int i = 0; i < 4; i++) acc[mt][nt][i] = 0.0f;

    float4 ra[4], rb[4];

    #pragma unroll
    for (int j = 0; j < 4; j++) {
        int m = a_m + 32 * j;
        int gr = row0 + m;
        ra[j] = (gr < M)
            ? *reinterpret_cast<const float4*>(A + (size_t)gr * KDIM + a_kq * 4)
            : make_float4(0.f, 0.f, 0.f, 0.f);
        rb[j] = *reinterpret_cast<const float4*>(B + (size_t)b_k * NDIM + col0 + b_n4 + 32 * j);
    }
    {
        #pragma unroll
        for (int j = 0; j < 4; j++) {
            int m = a_m + 32 * j;
            const float* v = &ra[j].x;
            #pragma unroll
            for (int i = 0; i < 4; i++) {
                int k = a_kq * 4 + i;
                As[0][k * BM + (m ^ swz(k))] = f2tf32(v[i]);
            }
            int n = b_n4 + 32 * j;
            const float* w = &rb[j].x;
            uint32_t* dst = &Bsm[0][b_k * BN + (n ^ swz(b_k))];
            #pragma unroll
            for (int i = 0; i < 4; i++) dst[i] = f2tf32(w[i]);
        }
    }
    __syncthreads();

    int st = 0;
    for (int it = 0; it < NIT; ++it) {
        if (it + 1 < NIT) {
            int k0 = (it + 1) * BK;
            #pragma unroll
            for (int j = 0; j < 4; j++) {
                int m = a_m + 32 * j;
                int gr = row0 + m;
                ra[j] = (gr < M)
                    ? *reinterpret_cast<const float4*>(A + (size_t)gr * KDIM + k0 + a_kq * 4)
                    : make_float4(0.f, 0.f, 0.f, 0.f);
                rb[j] = *reinterpret_cast<const float4*>(B + (size_t)(k0 + b_k) * NDIM + col0 + b_n4 + 32 * j);
            }
        }

        #pragma unroll
        for (int ks = 0; ks < BK; ks += 8) {
            const int k1 = ks + tig;
            const int k2 = ks + tig + 4;
            const int sx1 = swz(k1);
            const int sx2 = swz(k2);

            uint32_t af[4][4];
            #pragma unroll
            for (int mt = 0; mt < 4; mt++) {
                int r1 = wm * 64 + mt * 16 + gid;
                af[mt][0] = As[st][k1 * BM + (r1 ^ sx1)];
                af[mt][1] = As[st][k1 * BM + ((r1 + 8) ^ sx1)];
                af[mt][2] = As[st][k2 * BM + (r1 ^ sx2)];
                af[mt][3] = As[st][k2 * BM + ((r1 + 8) ^ sx2)];
            }
            uint32_t bf[8][2];
            #pragma unroll
            for (int nt = 0; nt < 8; nt++) {
                int cn = wn * 64 + nt * 8 + gid;
                bf[nt][0] = Bsm[st][k1 * BN + (cn ^ sx1)];
                bf[nt][1] = Bsm[st][k2 * BN + (cn ^ sx2)];
            }
            #pragma unroll
            for (int mt = 0; mt < 4; mt++)
                #pragma unroll
                for (int nt = 0; nt < 8; nt++)
                    mma_tf32(acc[mt][nt], af[mt][0], af[mt][1], af[mt][2], af[mt][3],
                             bf[nt][0], bf[nt][1]);
        }

        if (it + 1 < NIT) {
            int so = st ^ 1;
            #pragma unroll
            for (int j = 0; j < 4; j++) {
                int m = a_m + 32 * j;
                const float* v = &ra[j].x;
                #pragma unroll
                for (int i = 0; i < 4; i++) {
                    int k = a_kq * 4 + i;
                    As[so][k * BM + (m ^ swz(k))] = f2tf32(v[i]);
                }
                int n = b_n4 + 32 * j;
                const float* w = &rb[j].x;
                uint32_t* dst = &Bsm[so][b_k * BN + (n ^ swz(b_k))];
                #pragma unroll
                for (int i = 0; i < 4; i++) dst[i] = f2tf32(w[i]);
            }
            __syncthreads();
            st = so;
        }
    }

    // ---- epilogue ----
    #pragma unroll
    for (int mt = 0; mt < 4; mt++) {
        int r1 = row0 + wm * 64 + mt * 16 + gid;
        int r2 = r1 + 8;
        float s1 = 1.0f, s2 = 1.0f;
        if (SCALE_DINV) {
            if (r1 < M) s1 = g_dinv[r1];
            if (r2 < M) s2 = g_dinv[r2];
        }
        #pragma unroll
        for (int nt = 0; nt < 8; nt++) {
            int col = col0 + wn * 64 + nt * 8 + tig * 2;
            if (r1 < M) {
                if (OUT_HALF) {
                    __half2 v = __floats2half2_rn(acc[mt][nt][0] * s1, acc[mt][nt][1] * s1);
                    *reinterpret_cast<__half2*>((__half*)Cv + coff + (size_t)r1 * NDIM + col) = v;
                } else {
                    float2 v = make_float2(acc[mt][nt][0] * s1, acc[mt][nt][1] * s1);
                    *reinterpret_cast<float2*>((float*)Cv + coff + (size_t)r1 * NDIM + col) = v;
                }
            }
            if (r2 < M) {
                if (OUT_HALF) {
                    __half2 v = __floats2half2_rn(acc[mt][nt][2] * s2, acc[mt][nt][3] * s2);
                    *reinterpret_cast<__half2*>((__half*)Cv + coff + (size_t)r2 * NDIM + col) = v;
                } else {
                    float2 v = make_float2(acc[mt][nt][2] * s2, acc[mt][nt][3] * s2);
                    *reinterpret_cast<float2*>((float*)Cv + coff + (size_t)r2 * NDIM + col) = v;
                }
            }
        }
    }
}

// ---------------- Kernel C: SpMM over fp16 rows ------------------------------
// Y = f(an @ X) with pre-scaled fp16 X. 4 rows/block, 64 lanes/row; each lane
// owns 4 halfs (one uint2 = 2x half2). Chunks of 4 neighbors are summed in
// half2 (6 HADD2) then folded into fp32 accumulators once per chunk.
// MID=true:  out = fp16, dinv*relu(dinv*acc)   (middle layer)
// MID=false: out = fp32, dinv*acc              (final g)
template<bool MID>
__global__ __launch_bounds__(256)
void k_spmm(const uint2* __restrict__ X, void* __restrict__ Yv)
{
    const int sub  = threadIdx.x >> 6;              // 0..3 row within block
    const int lane = threadIdx.x & 63;              // 0..63 column group
    const int row  = blockIdx.x * 4 + sub;

    __shared__ int s_cols[4][CAP];
    const int cnt = g_cnt[row];
    {
        const int* __restrict__ cols = g_cols + (size_t)row * CAP;
        for (int k = lane; k < cnt; k += 64) s_cols[sub][k] = cols[k];
    }
    __syncthreads();

    const int* __restrict__ sc = s_cols[sub];
    const int HV = HH / 4;                          // 64 uint2 per row

    // self term
    float2 acc0, acc1;
    {
        uint2 u = X[(size_t)row * HV + lane];
        acc0 = __half22float2(*reinterpret_cast<__half2*>(&u.x));
        acc1 = __half22float2(*reinterpret_cast<__half2*>(&u.y));
    }

    int k = 0;
    for (; k + 4 <= cnt; k += 4) {
        uint2 u0 = X[(size_t)sc[k]     * HV + lane];
        uint2 u1 = X[(size_t)sc[k + 1] * HV + lane];
        uint2 u2 = X[(size_t)sc[k + 2] * HV + lane];
        uint2 u3 = X[(size_t)sc[k + 3] * HV + lane];
        __half2 s0 = __hadd2(__hadd2(*reinterpret_cast<__half2*>(&u0.x),
                                     *reinterpret_cast<__half2*>(&u1.x)),
                             __hadd2(*reinterpret_cast<__half2*>(&u2.x),
                                     *reinterpret_cast<__half2*>(&u3.x)));
        __half2 s1 = __hadd2(__hadd2(*reinterpret_cast<__half2*>(&u0.y),
                                     *reinterpret_cast<__half2*>(&u1.y)),
                             __hadd2(*reinterpret_cast<__half2*>(&u2.y),
                                     *reinterpret_cast<__half2*>(&u3.y)));
        float2 f0 = __half22float2(s0);
        float2 f1 = __half22float2(s1);
        acc0.x += f0.x; acc0.y += f0.y;
        acc1.x += f1.x; acc1.y += f1.y;
    }
    for (; k < cnt; k++) {
        uint2 u = X[(size_t)sc[k] * HV + lane];
        float2 f0 = __half22float2(*reinterpret_cast<__half2*>(&u.x));
        float2 f1 = __half22float2(*reinterpret_cast<__half2*>(&u.y));
        acc0.x += f0.x; acc0.y += f0.y;
        acc1.x += f1.x; acc1.y += f1.y;
    }

    const float di = g_dinv[row];
    if (MID) {
        float o0 = di * fmaxf(di * acc0.x, 0.0f);
        float o1 = di * fmaxf(di * acc0.y, 0.0f);
        float o2 = di * fmaxf(di * acc1.x, 0.0f);
        float o3 = di * fmaxf(di * acc1.y, 0.0f);
        uint2 o;
        *reinterpret_cast<__half2*>(&o.x) = __floats2half2_rn(o0, o1);
        *reinterpret_cast<__half2*>(&o.y) = __floats2half2_rn(o2, o3);
        reinterpret_cast<uint2*>(Yv)[(size_t)row * HV + lane] = o;
    } else {
        float4 o = make_float4(di * acc0.x, di * acc0.y, di * acc1.x, di * acc1.y);
        reinterpret_cast<float4*>(Yv)[(size_t)row * HV + lane] = o;
    }
}

// ---------------- launch ----------------
extern "C" void kernel_launch(void* const* d_in, const int* in_sizes, int n_in,
                              void* d_out, int out_size)
{
    const float* adj = (const float*)d_in[0];   // [N, N]
    const float* x   = (const float*)d_in[1];   // [N, D]
    const float* W1  = (const float*)d_in[2];   // [D, H]
    const float* Wm  = (const float*)d_in[3];   // [H, O]
    const float* Ws  = (const float*)d_in[4];   // [H, O]
    float* out = (float*)d_out;                 // [2, N, O]

    __half* xw; cudaGetSymbolAddress((void**)&xw, g_xw);
    __half* h;  cudaGetSymbolAddress((void**)&h,  g_h);
    float*  g;  cudaGetSymbolAddress((void**)&g,  g_g);
    int*    cntL; cudaGetSymbolAddress((void**)&cntL, g_cntL);

    const int mtiles = (NN + 127) / 128;        // 79

    // 1. zero counters (memset node), warp-per-row UT scan, deterministic merge
    cudaMemsetAsync(cntL, 0, NN * sizeof(int));
    k_scan_ut<<<NN / 8, 256>>>(adj);
    k_merge<<<(NN + 7) / 8, 256>>>();

    // 2. u = dinv .* (x @ W1) -> fp16
    k_mma<DD, true, false, true><<<dim3(HH / 128, mtiles), 128>>>(x, W1, nullptr, xw, NN, HH);

    // 3. hs = dinv .* relu(an @ (x@W1)) -> fp16
    k_spmm<true><<<NN / 4, 256>>>((const uint2*)xw, h);

    // 4. g = an @ h -> fp32
    k_spmm<false><<<NN / 4, 256>>>((const uint2*)h, g);

    // 5. z_mean = g @ Wm ; z_log_std = g @ Ws  (fp32 out)
    k_mma<HH, false, true, false><<<dim3(2, mtiles), 128>>>(g, Wm, Ws, out, NN, OO);
}

// round 10
// speedup vs baseline: 1.9394x; 1.2367x over previous
#include <cuda_runtime.h>
#include <cuda_fp16.h>
#include <math.h>
#include <stdint.h>

#define NN 10000
#define DD 512
#define HH 256
#define OO 128
#define CAP 128          // final merged neighbor cap per row
#define CAPH 96          // cap per half (upper / lower)
#define LCAP 16          // per-lane local buffer in scan

// ---------------- scratch (static device memory; no allocations) -------------
__device__ int    g_cols [(size_t)NN * CAP];    // merged neighbor lists
__device__ int    g_cnt  [NN];                  // merged nnz per row
__device__ float  g_dinv [NN];                  // rsqrt(degree)
__device__ int    g_colsU[(size_t)NN * CAPH];   // upper-tri neighbors (own scan)
__device__ int    g_cntU [NN];
__device__ int    g_colsL[(size_t)NN * CAPH];   // lower-tri neighbors (atomic scatter)
__device__ int    g_cntL [NN];
__device__ __half g_xw  [(size_t)NN * HH];      // x @ W1 (later scaled by dinv), fp16
__device__ __half g_h   [(size_t)NN * HH];      // hs = dinv .* relu(an @ xw), fp16
__device__ float  g_g   [(size_t)NN * HH];      // g  = an @ h, fp32

// ---------------- Kernel A: upper-triangle scan, warp-per-row ----------------
__global__ __launch_bounds__(256)
void k_scan_ut(const float* __restrict__ adj)
{
    const int lane = threadIdx.x & 31;
    const int row  = blockIdx.x * 8 + (threadIdx.x >> 5);
    const uint32_t* __restrict__ arow =
        reinterpret_cast<const uint32_t*>(adj + (size_t)row * NN);

    int local[LCAP];
    int lc = 0;

    const int start = row + 1;
    int aligned = (start + 15) & ~15;
    if (aligned > NN) aligned = NN;

    {
        int c = start + lane;
        if (c < aligned && arow[c] != 0u) { local[lc] = c; lc++; }
    }

    const uint4* __restrict__ arow4 = reinterpret_cast<const uint4*>(arow);
    const int base = aligned >> 4;
    const int nch  = NN >> 4;
    for (int t = base + lane; t < nch; t += 32) {
        const uint4* p = arow4 + 4 * t;
        uint4 w0 = p[0], w1 = p[1], w2 = p[2], w3 = p[3];
        uint32_t m = ((w0.x | w0.y) | (w0.z | w0.w))
                   | ((w1.x | w1.y) | (w1.z | w1.w))
                   | ((w2.x | w2.y) | (w2.z | w2.w))
                   | ((w3.x | w3.y) | (w3.z | w3.w));
        if (m != 0u) {
            const int c0 = t << 4;
            #define CHK(w, off) if ((w) != 0u) { if (lc < LCAP) local[lc] = c0 + (off); lc++; }
            CHK(w0.x, 0)  CHK(w0.y, 1)  CHK(w0.z, 2)  CHK(w0.w, 3)
            CHK(w1.x, 4)  CHK(w1.y, 5)  CHK(w1.z, 6)  CHK(w1.w, 7)
            CHK(w2.x, 8)  CHK(w2.y, 9)  CHK(w2.z, 10) CHK(w2.w, 11)
            CHK(w3.x, 12) CHK(w3.y, 13) CHK(w3.z, 14) CHK(w3.w, 15)
            #undef CHK
        }
    }
    if (lc > LCAP) lc = LCAP;

    int inc = lc;
    #pragma unroll
    for (int d = 1; d < 32; d <<= 1) {
        int n = __shfl_up_sync(0xffffffffu, inc, d);
        if (lane >= d) inc += n;
    }
    const int pos   = inc - lc;
    const int total = __shfl_sync(0xffffffffu, inc, 31);

    int* __restrict__ ucols = g_colsU + (size_t)row * CAPH;
    for (int i = 0; i < lc; i++) {
        int c = local[i];
        int p = pos + i;
        if (p < CAPH) ucols[p] = c;
        int lp = atomicAdd(&g_cntL[c], 1);
        if (lp < CAPH) g_colsL[(size_t)c * CAPH + lp] = row;
    }
    if (lane == 0) {
        int t = total;
        if (t > CAPH) t = CAPH;
        g_cntU[row] = t;
    }
}

// ---------------- Kernel M: merge L (sorted) + U -> g_cols, cnt, dinv --------
__global__ __launch_bounds__(256)
void k_merge()
{
    const int lane = threadIdx.x & 31;
    const int row  = blockIdx.x * 8 + (threadIdx.x >> 5);
    if (row >= NN) return;

    int cntL = g_cntL[row]; if (cntL > CAPH) cntL = CAPH;
    int cntU = g_cntU[row]; if (cntU > CAPH) cntU = CAPH;
    int total = cntL + cntU; if (total > CAP) total = CAP;

    const int* __restrict__ L = g_colsL + (size_t)row * CAPH;
    const int* __restrict__ U = g_colsU + (size_t)row * CAPH;
    int* __restrict__ dst = g_cols + (size_t)row * CAP;

    for (int s = lane; s < cntL; s += 32) {
        int v = L[s];
        int rank = 0;
        for (int j = 0; j < cntL; j++) rank += (L[j] < v) ? 1 : 0;
        if (rank < CAP) dst[rank] = v;
    }
    for (int k = lane; k < cntU; k += 32) {
        int p = cntL + k;
        if (p < CAP) dst[p] = U[k];
    }
    if (lane == 0) {
        g_cnt[row]  = total;
        g_dinv[row] = rsqrtf((float)total + 1.0f);
    }
}

// ---------------- Kernel S: xw *= dinv (row-wise), fp16 ----------------------
__global__ __launch_bounds__(256)
void k_scale()
{
    const int idx = blockIdx.x * 256 + threadIdx.x;   // uint2 index (4 halfs)
    const int row = idx >> 6;                         // HH/4 = 64 uint2 per row
    uint2 u = reinterpret_cast<uint2*>(g_xw)[idx];
    const float d = g_dinv[row];
    const __half2 dh = __floats2half2_rn(d, d);
    __half2 a = __hmul2(*reinterpret_cast<__half2*>(&u.x), dh);
    __half2 b = __hmul2(*reinterpret_cast<__half2*>(&u.y), dh);
    u.x = *reinterpret_cast<uint32_t*>(&a);
    u.y = *reinterpret_cast<uint32_t*>(&b);
    reinterpret_cast<uint2*>(g_xw)[idx] = u;
}

// ---------------- tf32 helpers ----------------
__device__ __forceinline__ uint32_t f2tf32(float x)
{
    uint32_t r;
    asm("cvt.rna.tf32.f32 %0, %1;" : "=r"(r) : "f"(x));
    return r;
}

__device__ __forceinline__ void mma_tf32(float c[4],
    uint32_t a0, uint32_t a1, uint32_t a2, uint32_t a3,
    uint32_t b0, uint32_t b1)
{
    asm volatile(
        "mma.sync.aligned.m16n8k8.row.col.f32.tf32.tf32.f32 "
        "{%0,%1,%2,%3}, {%4,%5,%6,%7}, {%8,%9}, {%0,%1,%2,%3};"
        : "+f"(c[0]), "+f"(c[1]), "+f"(c[2]), "+f"(c[3])
        : "r"(a0), "r"(a1), "r"(a2), "r"(a3), "r"(b0), "r"(b1));
}

__device__ __forceinline__ int swz(int k)
{
    return ((k & 3) ^ ((k >> 2) & 3)) << 3;
}

// ---------------- Kernel B: tf32 tensor-core GEMM  (R4 proven config) -------
// BM=BN=128, BK=16, 128 threads (4 warps, 64x64 warp tiles), double-buffered.
// OUT_HALF: write C as fp16 (__half2 pairs) instead of fp32.
template<int KDIM, bool SCALE_DINV, bool DUAL_B, bool OUT_HALF>
__global__ __launch_bounds__(128)
void k_mma(const float* __restrict__ A, const float* __restrict__ Bm,
           const float* __restrict__ Bs2, void* __restrict__ Cv,
           int M, int NDIM)
{
    const int BM = 128, BN = 128, BK = 16;
    const int NIT = KDIM / BK;
    __shared__ uint32_t As[2][BK * BM];
    __shared__ uint32_t Bsm[2][BK * BN];

    const int tid  = threadIdx.x;
    const int lane = tid & 31;
    const int warp = tid >> 5;
    const int wm   = warp >> 1;
    const int wn   = warp & 1;
    const int gid  = lane >> 2;
    const int tig  = lane & 3;

    const int row0 = blockIdx.y * BM;
    const float* __restrict__ B = DUAL_B ? (blockIdx.x ? Bs2 : Bm) : Bm;
    const int col0 = DUAL_B ? 0 : blockIdx.x * BN;
    const size_t coff = DUAL_B ? (size_t)blockIdx.x * (size_t)M * NDIM : 0;

    const int a_m  = tid >> 2;
    const int a_kq = tid & 3;
    const int b_k  = tid >> 3;
    const int b_n4 = (tid & 7) * 4;

    float acc[4][8][4];
    #pragma unroll
    for (int mt = 0; mt < 4; mt++)
        #pragma unroll
        for (int nt = 0; nt < 8; nt++)
            #pragma unroll
            for (int i = 0; i < 4; i++) acc[mt][nt][i] = 0.0f;

    float4 ra[4], rb[4];

    #pragma unroll
    for (int j = 0; j < 4; j++) {
        int m = a_m + 32 * j;
        int gr = row0 + m;
        ra[j] = (gr < M)
            ? *reinterpret_cast<const float4*>(A + (size_t)gr * KDIM + a_kq * 4)
            : make_float4(0.f, 0.f, 0.f, 0.f);
        rb[j] = *reinterpret_cast<const float4*>(B + (size_t)b_k * NDIM + col0 + b_n4 + 32 * j);
    }
    {
        #pragma unroll
        for (int j = 0; j < 4; j++) {
            int m = a_m + 32 * j;
            const float* v = &ra[j].x;
            #pragma unroll
            for (int i = 0; i < 4; i++) {
                int k = a_kq * 4 + i;
                As[0][k * BM + (m ^ swz(k))] = f2tf32(v[i]);
            }
            int n = b_n4 + 32 * j;
            const float* w = &rb[j].x;
            uint32_t* dst = &Bsm[0][b_k * BN + (n ^ swz(b_k))];
            #pragma unroll
            for (int i = 0; i < 4; i++) dst[i] = f2tf32(w[i]);
        }
    }
    __syncthreads();

    int st = 0;
    for (int it = 0; it < NIT; ++it) {
        if (it + 1 < NIT) {
            int k0 = (it + 1) * BK;
            #pragma unroll
            for (int j = 0; j < 4; j++) {
                int m = a_m + 32 * j;
                int gr = row0 + m;
                ra[j] = (gr < M)
                    ? *reinterpret_cast<const float4*>(A + (size_t)gr * KDIM + k0 + a_kq * 4)
                    : make_float4(0.f, 0.f, 0.f, 0.f);
                rb[j] = *reinterpret_cast<const float4*>(B + (size_t)(k0 + b_k) * NDIM + col0 + b_n4 + 32 * j);
            }
        }

        #pragma unroll
        for (int ks = 0; ks < BK; ks += 8) {
            const int k1 = ks + tig;
            const int k2 = ks + tig + 4;
            const int sx1 = swz(k1);
            const int sx2 = swz(k2);

            uint32_t af[4][4];
            #pragma unroll
            for (int mt = 0; mt < 4; mt++) {
                int r1 = wm * 64 + mt * 16 + gid;
                af[mt][0] = As[st][k1 * BM + (r1 ^ sx1)];
                af[mt][1] = As[st][k1 * BM + ((r1 + 8) ^ sx1)];
                af[mt][2] = As[st][k2 * BM + (r1 ^ sx2)];
                af[mt][3] = As[st][k2 * BM + ((r1 + 8) ^ sx2)];
            }
            uint32_t bf[8][2];
            #pragma unroll
            for (int nt = 0; nt < 8; nt++) {
                int cn = wn * 64 + nt * 8 + gid;
                bf[nt][0] = Bsm[st][k1 * BN + (cn ^ sx1)];
                bf[nt][1] = Bsm[st][k2 * BN + (cn ^ sx2)];
            }
            #pragma unroll
            for (int mt = 0; mt < 4; mt++)
                #pragma unroll
                for (int nt = 0; nt < 8; nt++)
                    mma_tf32(acc[mt][nt], af[mt][0], af[mt][1], af[mt][2], af[mt][3],
                             bf[nt][0], bf[nt][1]);
        }

        if (it + 1 < NIT) {
            int so = st ^ 1;
            #pragma unroll
            for (int j = 0; j < 4; j++) {
                int m = a_m + 32 * j;
                const float* v = &ra[j].x;
                #pragma unroll
                for (int i = 0; i < 4; i++) {
                    int k = a_kq * 4 + i;
                    As[so][k * BM + (m ^ swz(k))] = f2tf32(v[i]);
                }
                int n = b_n4 + 32 * j;
                const float* w = &rb[j].x;
                uint32_t* dst = &Bsm[so][b_k * BN + (n ^ swz(b_k))];
                #pragma unroll
                for (int i = 0; i < 4; i++) dst[i] = f2tf32(w[i]);
            }
            __syncthreads();
            st = so;
        }
    }

    // ---- epilogue ----
    #pragma unroll
    for (int mt = 0; mt < 4; mt++) {
        int r1 = row0 + wm * 64 + mt * 16 + gid;
        int r2 = r1 + 8;
        float s1 = 1.0f, s2 = 1.0f;
        if (SCALE_DINV) {
            if (r1 < M) s1 = g_dinv[r1];
            if (r2 < M) s2 = g_dinv[r2];
        }
        #pragma unroll
        for (int nt = 0; nt < 8; nt++) {
            int col = col0 + wn * 64 + nt * 8 + tig * 2;
            if (r1 < M) {
                if (OUT_HALF) {
                    __half2 v = __floats2half2_rn(acc[mt][nt][0] * s1, acc[mt][nt][1] * s1);
                    *reinterpret_cast<__half2*>((__half*)Cv + coff + (size_t)r1 * NDIM + col) = v;
                } else {
                    float2 v = make_float2(acc[mt][nt][0] * s1, acc[mt][nt][1] * s1);
                    *reinterpret_cast<float2*>((float*)Cv + coff + (size_t)r1 * NDIM + col) = v;
                }
            }
            if (r2 < M) {
                if (OUT_HALF) {
                    __half2 v = __floats2half2_rn(acc[mt][nt][2] * s2, acc[mt][nt][3] * s2);
                    *reinterpret_cast<__half2*>((__half*)Cv + coff + (size_t)r2 * NDIM + col) = v;
                } else {
                    float2 v = make_float2(acc[mt][nt][2] * s2, acc[mt][nt][3] * s2);
                    *reinterpret_cast<float2*>((float*)Cv + coff + (size_t)r2 * NDIM + col) = v;
                }
            }
        }
    }
}

// ---------------- Kernel C: SpMM over fp16 rows ------------------------------
template<bool MID>
__global__ __launch_bounds__(256)
void k_spmm(const uint2* __restrict__ X, void* __restrict__ Yv)
{
    const int sub  = threadIdx.x >> 6;
    const int lane = threadIdx.x & 63;
    const int row  = blockIdx.x * 4 + sub;

    __shared__ int s_cols[4][CAP];
    const int cnt = g_cnt[row];
    {
        const int* __restrict__ cols = g_cols + (size_t)row * CAP;
        for (int k = lane; k < cnt; k += 64) s_cols[sub][k] = cols[k];
    }
    __syncthreads();

    const int* __restrict__ sc = s_cols[sub];
    const int HV = HH / 4;

    float2 acc0, acc1;
    {
        uint2 u = X[(size_t)row * HV + lane];
        acc0 = __half22float2(*reinterpret_cast<__half2*>(&u.x));
        acc1 = __half22float2(*reinterpret_cast<__half2*>(&u.y));
    }

    int k = 0;
    for (; k + 4 <= cnt; k += 4) {
        uint2 u0 = X[(size_t)sc[k]     * HV + lane];
        uint2 u1 = X[(size_t)sc[k + 1] * HV + lane];
        uint2 u2 = X[(size_t)sc[k + 2] * HV + lane];
        uint2 u3 = X[(size_t)sc[k + 3] * HV + lane];
        __half2 s0 = __hadd2(__hadd2(*reinterpret_cast<__half2*>(&u0.x),
                                     *reinterpret_cast<__half2*>(&u1.x)),
                             __hadd2(*reinterpret_cast<__half2*>(&u2.x),
                                     *reinterpret_cast<__half2*>(&u3.x)));
        __half2 s1 = __hadd2(__hadd2(*reinterpret_cast<__half2*>(&u0.y),
                                     *reinterpret_cast<__half2*>(&u1.y)),
                             __hadd2(*reinterpret_cast<__half2*>(&u2.y),
                                     *reinterpret_cast<__half2*>(&u3.y)));
        float2 f0 = __half22float2(s0);
        float2 f1 = __half22float2(s1);
        acc0.x += f0.x; acc0.y += f0.y;
        acc1.x += f1.x; acc1.y += f1.y;
    }
    for (; k < cnt; k++) {
        uint2 u = X[(size_t)sc[k] * HV + lane];
        float2 f0 = __half22float2(*reinterpret_cast<__half2*>(&u.x));
        float2 f1 = __half22float2(*reinterpret_cast<__half2*>(&u.y));
        acc0.x += f0.x; acc0.y += f0.y;
        acc1.x += f1.x; acc1.y += f1.y;
    }

    const float di = g_dinv[row];
    if (MID) {
        float o0 = di * fmaxf(di * acc0.x, 0.0f);
        float o1 = di * fmaxf(di * acc0.y, 0.0f);
        float o2 = di * fmaxf(di * acc1.x, 0.0f);
        float o3 = di * fmaxf(di * acc1.y, 0.0f);
        uint2 o;
        *reinterpret_cast<__half2*>(&o.x) = __floats2half2_rn(o0, o1);
        *reinterpret_cast<__half2*>(&o.y) = __floats2half2_rn(o2, o3);
        reinterpret_cast<uint2*>(Yv)[(size_t)row * HV + lane] = o;
    } else {
        float4 o = make_float4(di * acc0.x, di * acc0.y, di * acc1.x, di * acc1.y);
        reinterpret_cast<float4*>(Yv)[(size_t)row * HV + lane] = o;
    }
}

// ---------------- launch ----------------
extern "C" void kernel_launch(void* const* d_in, const int* in_sizes, int n_in,
                              void* d_out, int out_size)
{
    const float* adj = (const float*)d_in[0];   // [N, N]
    const float* x   = (const float*)d_in[1];   // [N, D]
    const float* W1  = (const float*)d_in[2];   // [D, H]
    const float* Wm  = (const float*)d_in[3];   // [H, O]
    const float* Ws  = (const float*)d_in[4];   // [H, O]
    float* out = (float*)d_out;                 // [2, N, O]

    __half* xw; cudaGetSymbolAddress((void**)&xw, g_xw);
    __half* h;  cudaGetSymbolAddress((void**)&h,  g_h);
    float*  g;  cudaGetSymbolAddress((void**)&g,  g_g);
    int*    cntL; cudaGetSymbolAddress((void**)&cntL, g_cntL);

    const int mtiles = (NN + 127) / 128;        // 79

    // fresh stream/events each call (host-side only; not destroyed to avoid
    // invalidating an in-progress capture — a handful of calls total)
    cudaStream_t s2;
    cudaEvent_t evFork, evJoin;
    cudaStreamCreateWithFlags(&s2, cudaStreamNonBlocking);
    cudaEventCreateWithFlags(&evFork, cudaEventDisableTiming);
    cudaEventCreateWithFlags(&evJoin, cudaEventDisableTiming);

    // ---- fork: mma1 (graph-independent) on side stream ----
    cudaEventRecord(evFork, 0);
    cudaStreamWaitEvent(s2, evFork, 0);
    // xw = x @ W1 (unscaled) -> fp16
    k_mma<DD, false, false, true><<<dim3(HH / 128, mtiles), 128, 0, s2>>>(
        x, W1, nullptr, xw, NN, HH);
    cudaEventRecord(evJoin, s2);

    // ---- main stream: graph preprocessing (concurrent with mma1) ----
    cudaMemsetAsync(cntL, 0, NN * sizeof(int));
    k_scan_ut<<<NN / 8, 256>>>(adj);
    k_merge<<<(NN + 7) / 8, 256>>>();

    // ---- join, then scale xw by dinv ----
    cudaStreamWaitEvent(0, evJoin, 0);
    k_scale<<<(NN * HH / 4) / 256, 256>>>();    // xw *= dinv (row-wise)

    // hs = dinv .* relu(an @ xw) -> fp16
    k_spmm<true><<<NN / 4, 256>>>((const uint2*)xw, h);

    // g = an @ h -> fp32
    k_spmm<false><<<NN / 4, 256>>>((const uint2*)h, g);

    // z_mean = g @ Wm ; z_log_std = g @ Ws  (fp32 out)
    k_mma<HH, false, true, false><<<dim3(2, mtiles), 128>>>(g, Wm, Ws, out, NN, OO);
}